// round 15
// baseline (speedup 1.0000x reference)
#include <cuda_runtime.h>
#include <cuda_bf16.h>

// Shapes: A=1, B=8, M=256, H(=Kdim)=2048, E=8, K=2, N=2048
// out (scalar) = sum_{b,e,k} sp[b,e] * hsum[b,k] * wsum[e,k]
//   hsum[b,k] = sum_m hidden[0,b,m,k]     (16 MB stream)
//   wsum[e,k] = sum_n W[0,e,k,n]          (134 MB stream)
//
// Two kernels (stream at HBM ceiling + combine), PDL-launched secondary.
// R14 finding: 512 same-address atomicAdd(double) serialized ~7us in the
// combine. This version uses per-block smem reduction + plain slot stores +
// a 16-entry final sum -> no contended value atomics at all.

#define Bd 8
#define Md 256
#define Hd 2048
#define Ed 8
#define Nd 2048

#define W_BLOCKS   2048            // 8 warps/block, 1 warp per (e,k) row
#define H_BLOCKS   256             // 16 m-chunks x 16 k-blocks
#define MCHUNKS    16

#define C_BLOCKS   16              // combine: 16 blocks x 1024 threads

__device__ float  g_wsum[Ed * Hd];            // 64 KB
__device__ float  g_part[MCHUNKS * Bd * Hd];  // 1 MB partial hidden sums
__device__ double g_slots[C_BLOCKS];
__device__ unsigned int g_done;

// ---------------- kernel 1: all 150 MB of streaming, one wave-set ----------------
__global__ void __launch_bounds__(256) k_stream(const float* __restrict__ W,
                                                const float* __restrict__ hidden) {
    if (blockIdx.x == 0 && threadIdx.x == 0) g_done = 0u;

    if (blockIdx.x < W_BLOCKS) {
        // ---- W row sums: one warp per row of 2048 floats ----
        int warp = threadIdx.x >> 5;
        int lane = threadIdx.x & 31;
        int row  = blockIdx.x * 8 + warp;            // e*2048 + k

        const float4* src = reinterpret_cast<const float4*>(W + (size_t)row * Nd);
        float s = 0.f;
#pragma unroll
        for (int i = 0; i < 16; i++) {               // 16 f4 * 32 lanes = 2048 floats
            float4 v = src[lane + 32 * i];
            s += (v.x + v.y) + (v.z + v.w);
        }
#pragma unroll
        for (int off = 16; off > 0; off >>= 1)
            s += __shfl_xor_sync(0xffffffff, s, off);
        if (lane == 0) g_wsum[row] = s;
    } else {
        // ---- hidden partial column sums: 64 KB per block, plain stores ----
        int idx = blockIdx.x - W_BLOCKS;             // 0..255
        int mc  = idx >> 4;                          // m chunk (0..15)
        int kb  = idx & 15;                          // k4 block (0..15)
        int g   = kb * 256 + threadIdx.x;            // 0..4095 = b*512 + k4
        int b   = g >> 9;
        int k4  = g & 511;
        int m0  = mc * 16;

        const float4* src = reinterpret_cast<const float4*>(
            hidden + (size_t)(b * Md + m0) * Hd) + k4;

        float4 acc = make_float4(0.f, 0.f, 0.f, 0.f);
#pragma unroll
        for (int i = 0; i < 16; i++) {
            float4 v = src[i * (Hd / 4)];
            acc.x += v.x; acc.y += v.y; acc.z += v.z; acc.w += v.w;
        }
        reinterpret_cast<float4*>(g_part)[mc * 4096 + g] = acc;   // [c][b][k] layout
    }

    // Signal dependent grid (PDL): prior stores visible after its wait.
    asm volatile("griddepcontrol.launch_dependents;");
}

// ---------------- kernel 2: contraction, no contended atomics ----------------
// 16 blocks x 1024 threads; thread t owns (b = t>>11, k = t&2047).
__global__ void __launch_bounds__(1024) k_combine(const float* __restrict__ sp,
                                                  float* __restrict__ out) {
    __shared__ double s_red[32];
    const int tid  = threadIdx.x;
    const int warp = tid >> 5;
    const int lane = tid & 31;

    int t = blockIdx.x * 1024 + tid;                 // 0..16383
    int b = t >> 11;                                 // 0..7
    int k = t & 2047;                                // 0..2047

    // Prologue independent of primary: sp coefficients.
    float spc[Ed];
#pragma unroll
    for (int e = 0; e < Ed; e++)
        spc[e] = sp[b * 16 + e];                     // sp layout (b, K=2, e): slice 0

    asm volatile("griddepcontrol.wait;");            // no-op without PDL

    // hsum[b,k] = sum over 16 m-chunk partials (MLP=16, L2 hits)
    float hs = 0.f;
#pragma unroll
    for (int c = 0; c < MCHUNKS; c++)
        hs += g_part[c * (Bd * Hd) + b * Hd + k];

    // cb = sum_e sp[b,e] * wsum[e,k]
    float cb = 0.f;
#pragma unroll
    for (int e = 0; e < Ed; e++)
        cb += spc[e] * g_wsum[e * Hd + k];

    double acc = (double)hs * (double)cb;

    // block reduce: warp shuffle -> smem -> warp0
#pragma unroll
    for (int off = 16; off > 0; off >>= 1)
        acc += __shfl_xor_sync(0xffffffff, acc, off);
    if (lane == 0) s_red[warp] = acc;
    __syncthreads();
    if (warp == 0) {
        double d = s_red[lane];                      // 32 warps exactly
#pragma unroll
        for (int off = 16; off > 0; off >>= 1)
            d += __shfl_xor_sync(0xffffffff, d, off);
        if (lane == 0) {
            g_slots[blockIdx.x] = d;                 // plain store, no contention
            unsigned int tkt;
            asm volatile("atom.release.gpu.global.add.u32 %0, [%1], %2;"
                         : "=r"(tkt) : "l"(&g_done), "r"(1u) : "memory");
            if (tkt == C_BLOCKS - 1) {               // last block: all slots visible
                asm volatile("fence.acq_rel.gpu;" ::: "memory");
                double total = 0.0;
#pragma unroll
                for (int i = 0; i < C_BLOCKS; i++) total += g_slots[i];
                out[0] = (float)total;
            }
        }
    }
}

extern "C" void kernel_launch(void* const* d_in, const int* in_sizes, int n_in,
                              void* d_out, int out_size) {
    const float* hidden = (const float*)d_in[0];   // (1,8,256,2048)
    const float* sp     = (const float*)d_in[1];   // (1,8,2,8)
    const float* W      = (const float*)d_in[2];   // (1,8,2048,2048)
    float* out = (float*)d_out;

    k_stream<<<W_BLOCKS + H_BLOCKS, 256>>>(W, hidden);

    // Secondary with Programmatic Dependent Launch.
    cudaLaunchConfig_t cfg = {};
    cfg.gridDim  = dim3(C_BLOCKS, 1, 1);
    cfg.blockDim = dim3(1024, 1, 1);
    cfg.dynamicSmemBytes = 0;
    cfg.stream = (cudaStream_t)0;
    cudaLaunchAttribute attr[1];
    attr[0].id = cudaLaunchAttributeProgrammaticStreamSerialization;
    attr[0].val.programmaticStreamSerializationAllowed = 1;
    cfg.attrs = attr;
    cfg.numAttrs = 1;

    cudaError_t err = cudaLaunchKernelEx(&cfg, k_combine, sp, out);
    if (err != cudaSuccess) {
        k_combine<<<C_BLOCKS, 1024>>>(sp, out);      // fallback, still correct
    }
}